// round 6
// baseline (speedup 1.0000x reference)
#include <cuda_runtime.h>
#include <math.h>

#define Mpts 100000
#define Bb 8
#define Kk 512
#define Nn 256

#define BETA_F 13.85510032f       // pi*sqrt((J/ALPHA*(ALPHA-0.5))^2 - 0.8)
#define KSC 81.48733086f          // K/(2*pi)
#define PIJK 0.03681553891f       // pi*J/K

// fp32 grid: [cell][b], cell = row*K + col. 16 MB.
__device__ __align__(16) float2 g_grid[Kk * Kk * Bb];
// row-FFT output, pruned: [b][row(0..511)][j(0..255)]. 8 MB.
__device__ float2 g_grid2[Bb * Kk * Nn];
// real image after col-FFT + apod, TRANSPOSED: [b][c][r]. 2 MB.
__device__ float g_img[Bb * Nn * Nn];
__device__ int g_mm_i[2 * Bb];

// binning structures (32x32 tiles of 16x16 cells)
#define NT 1024
__device__ int g_cnt[NT];        // statically zero; reset by gather each call
__device__ int g_off[NT];
__device__ int g_cur[NT];
__device__ int g_list[420000];
__device__ __align__(16) float4 g_pinfo[Mpts];        // (bu, bv, fru, frv)
__device__ __align__(16) float4 g_ydata[Mpts * 4];    // weighted y, [m][b-pairs]

// ---------------- helpers ----------------
__device__ __forceinline__ float2 cmul(float2 a, float2 b) {
    return make_float2(a.x * b.x - a.y * b.y, a.x * b.y + a.y * b.x);
}
__device__ __forceinline__ float2 cadd(float2 a, float2 b) { return make_float2(a.x + b.x, a.y + b.y); }
__device__ __forceinline__ float2 csub(float2 a, float2 b) { return make_float2(a.x - b.x, a.y - b.y); }

__device__ __forceinline__ int fenc(float v) {
    int b = __float_as_int(v);
    return b >= 0 ? b : (b ^ 0x7fffffff);
}

// Bessel I0 (A&S 9.8.1/9.8.2)
__device__ __forceinline__ float i0f(float x) {
    float ax = fabsf(x);
    if (ax < 3.75f) {
        float t = x / 3.75f;
        t *= t;
        return 1.0f + t * (3.5156229f + t * (3.0899424f + t * (1.2067492f +
               t * (0.2659732f + t * (0.0360768f + t * 0.0045813f)))));
    } else {
        float t = 3.75f / ax;
        float p = 0.39894228f + t * (0.01328592f + t * (0.00225319f +
                  t * (-0.00157565f + t * (0.00916281f + t * (-0.02057706f +
                  t * (0.02635537f + t * (-0.01647633f + t * 0.00392377f)))))));
        return (expf(ax) / sqrtf(ax)) * p;
    }
}

__device__ __forceinline__ float apodinv(int n) {
    float x = (float)(n - 128) * PIJK;
    float a = BETA_F * BETA_F - x * x;
    float sq = sqrtf(a);
    return sq / sinhf(sq);
}

// touched-tile helper (same code in prep & fill)
__device__ __forceinline__ void touched(int bu, int bv, int* t4, int& nt) {
    int ta = ((bu - 2) & 511) >> 4, tb = ((bu + 3) & 511) >> 4;
    int ca = ((bv - 2) & 511) >> 4, cb = ((bv + 3) & 511) >> 4;
    nt = 0;
    t4[nt++] = ta * 32 + ca;
    if (cb != ca) t4[nt++] = ta * 32 + cb;
    if (tb != ta) {
        t4[nt++] = tb * 32 + ca;
        if (cb != ca) t4[nt++] = tb * 32 + cb;
    }
}

// ---------------- prep: point info + weighted y + tile counts ----------------
__global__ void __launch_bounds__(256) prep_k(
    const float* __restrict__ yr, const float* __restrict__ yi,
    const float* __restrict__ wt, const float* __restrict__ uv) {
    int m = blockIdx.x * 256 + threadIdx.x;
    if (blockIdx.x == 0 && threadIdx.x < 2 * Bb)
        g_mm_i[threadIdx.x] = (threadIdx.x & 1) ? (int)0x80000000 : 0x7fffffff;
    if (m >= Mpts) return;

    float u = uv[2 * m], v = uv[2 * m + 1];
    float kfu = u * KSC, kfv = v * KSC;
    float fbu = floorf(kfu), fbv = floorf(kfv);
    g_pinfo[m] = make_float4(fbu, fbv, kfu - fbu, kfv - fbv);

    float winv = 1.0f / i0f(BETA_F);
    float wm = wt[m] * winv * winv;
#pragma unroll
    for (int k = 0; k < 4; k++) {
        g_ydata[m * 4 + k] = make_float4(
            yr[(2 * k) * Mpts + m] * wm, yi[(2 * k) * Mpts + m] * wm,
            yr[(2 * k + 1) * Mpts + m] * wm, yi[(2 * k + 1) * Mpts + m] * wm);
    }

    int t4[4], nt;
    touched((int)fbu, (int)fbv, t4, nt);
    for (int k = 0; k < nt; k++) atomicAdd(&g_cnt[t4[k]], 1);
}

// ---------------- scan: exclusive prefix over 1024 tile counts --------------
__global__ void __launch_bounds__(1024) scan_k() {
    __shared__ int s[1024];
    int i = threadIdx.x;
    int v = g_cnt[i];
    s[i] = v;
    __syncthreads();
    for (int d = 1; d < 1024; d <<= 1) {
        int t = (i >= d) ? s[i - d] : 0;
        __syncthreads();
        s[i] += t;
        __syncthreads();
    }
    int off = s[i] - v;
    g_off[i] = off;
    g_cur[i] = off;
}

// ---------------- fill: scatter point indices into tile lists ----------------
__global__ void __launch_bounds__(256) fill_k(const float* __restrict__ uv) {
    int m = blockIdx.x * 256 + threadIdx.x;
    if (m >= Mpts) return;
    float kfu = uv[2 * m] * KSC, kfv = uv[2 * m + 1] * KSC;
    int bu = (int)floorf(kfu), bv = (int)floorf(kfv);
    int t4[4], nt;
    touched(bu, bv, t4, nt);
    for (int k = 0; k < nt; k++)
        g_list[atomicAdd(&g_cur[t4[k]], 1)] = m;
}

// ---------------- gather: one tile per block, one cell per thread -----------
__global__ void __launch_bounds__(256) gather_k() {
    __shared__ int lst[64];
    __shared__ float4 pinfo_s[64];
    __shared__ float4 y_s[64][4];
    __shared__ int s_off, s_cnt;

    int tile = blockIdx.x;
    int tr = tile >> 5, tc = tile & 31;
    int tid = threadIdx.x;
    int r = (tr << 4) + (tid >> 4), c = (tc << 4) + (tid & 15);

    // uniform off/cnt broadcast; reset happens strictly after the single read.
    if (tid == 0) {
        s_off = g_off[tile];
        s_cnt = g_cnt[tile];
        g_cnt[tile] = 0;      // reset for the next graph replay
    }
    __syncthreads();
    int off = s_off, cnt = s_cnt;

    float2 acc[8];
#pragma unroll
    for (int k = 0; k < 8; k++) acc[k] = make_float2(0.f, 0.f);

    for (int base = 0; base < cnt; base += 64) {
        int n = min(64, cnt - base);
        if (tid < n) lst[tid] = g_list[off + base + tid];
        __syncthreads();
        if (tid < n) pinfo_s[tid] = g_pinfo[lst[tid]];
        if ((tid >> 2) < n) y_s[tid >> 2][tid & 3] = g_ydata[lst[tid >> 2] * 4 + (tid & 3)];
        __syncthreads();
        for (int p = 0; p < n; p++) {
            float4 pi = pinfo_s[p];
            int bu = (int)pi.x, bv = (int)pi.y;
            int sr = (r - bu + 2) & 511, sc = (c - bv + 2) & 511;
            if (sr <= 5 && sc <= 5) {
                float du = (float)(sr - 2) - pi.z;
                float dv = (float)(sc - 2) - pi.w;
                float wu = i0f(BETA_F * sqrtf(fmaxf(1.0f - du * du * (1.0f / 9.0f), 0.0f)));
                float wv = i0f(BETA_F * sqrtf(fmaxf(1.0f - dv * dv * (1.0f / 9.0f), 0.0f)));
                float ww = wu * wv;
#pragma unroll
                for (int k = 0; k < 4; k++) {
                    float4 yv = y_s[p][k];
                    acc[2 * k].x     += ww * yv.x;
                    acc[2 * k].y     += ww * yv.y;
                    acc[2 * k + 1].x += ww * yv.z;
                    acc[2 * k + 1].y += ww * yv.w;
                }
            }
        }
        __syncthreads();
    }

    float4* dst = reinterpret_cast<float4*>(g_grid + ((size_t)(r * Kk + c)) * Bb);
#pragma unroll
    for (int k = 0; k < 4; k++)
        dst[k] = make_float4(acc[2 * k].x, acc[2 * k].y, acc[2 * k + 1].x, acc[2 * k + 1].y);
}

// ---------------- 512-pt inverse FFT, radix-8 Stockham, 64 threads per FFT ----
#define PIDX(i) ((i) + ((i) >> 3))

__device__ __forceinline__ void fft8p(const float2* x, float2* y) {
    const float C = 0.70710678118654752f;
    float2 a0 = cadd(x[0], x[4]), a4 = csub(x[0], x[4]);
    float2 a1 = cadd(x[1], x[5]), t5 = csub(x[1], x[5]);
    float2 a2 = cadd(x[2], x[6]), t6 = csub(x[2], x[6]);
    float2 a3 = cadd(x[3], x[7]), t7 = csub(x[3], x[7]);
    float2 a5 = make_float2(C * (t5.x - t5.y), C * (t5.x + t5.y));
    float2 a6 = make_float2(-t6.y, t6.x);
    float2 a7 = make_float2(-C * (t7.x + t7.y), C * (t7.x - t7.y));

    float2 b0 = cadd(a0, a2), b2 = csub(a0, a2);
    float2 b1 = cadd(a1, a3), t3 = csub(a1, a3);
    float2 b3 = make_float2(-t3.y, t3.x);
    float2 b4 = cadd(a4, a6), b6 = csub(a4, a6);
    float2 b5 = cadd(a5, a7), u7 = csub(a5, a7);
    float2 b7 = make_float2(-u7.y, u7.x);

    y[0] = cadd(b0, b1); y[4] = csub(b0, b1);
    y[2] = cadd(b2, b3); y[6] = csub(b2, b3);
    y[1] = cadd(b4, b5); y[5] = csub(b4, b5);
    y[3] = cadd(b6, b7); y[7] = csub(b6, b7);
}

__device__ __forceinline__ void twiddle8(float2* x, float ang) {
    float2 w1; __sincosf(ang, &w1.y, &w1.x);
    float2 w = w1;
    x[1] = cmul(x[1], w);
#pragma unroll
    for (int i = 2; i < 8; i++) { w = cmul(w, w1); x[i] = cmul(x[i], w); }
}

__device__ __forceinline__ void fft512(float2* S, int t, float2* y) {
    float2 x[8];
#pragma unroll
    for (int i = 0; i < 8; i++) x[i] = S[PIDX(t + 64 * i)];
    fft8p(x, y);
    __syncthreads();
#pragma unroll
    for (int i = 0; i < 8; i++) S[PIDX(8 * t + i)] = y[i];
    __syncthreads();
#pragma unroll
    for (int i = 0; i < 8; i++) x[i] = S[PIDX(t + 64 * i)];
    {
        int k = t & 7;
        twiddle8(x, 0.09817477042f * (float)k);   // 2*pi/64
    }
    fft8p(x, y);
    __syncthreads();
    {
        int k = t & 7, g = t >> 3;
#pragma unroll
        for (int i = 0; i < 8; i++) S[PIDX(g * 64 + i * 8 + k)] = y[i];
    }
    __syncthreads();
#pragma unroll
    for (int i = 0; i < 8; i++) x[i] = S[PIDX(t + 64 * i)];
    twiddle8(x, 0.01227184630f * (float)t);       // 2*pi/512
    fft8p(x, y);
}

// ---------------- FFT pass A: along axis 2 (columns). 8 batches / block -----
__global__ void __launch_bounds__(512) fftA_k() {
    __shared__ float2 s[8 * 577];
    int row = blockIdx.x;
    const float2* src = g_grid + (size_t)row * (Kk * Bb);
    for (int idx = threadIdx.x; idx < Kk * Bb; idx += 512) {
        int col = idx >> 3, b = idx & 7;
        s[b * 577 + PIDX(col)] = src[idx];
    }
    __syncthreads();

    int b = threadIdx.x >> 6, t = threadIdx.x & 63;
    float2 y[8];
    fft512(s + b * 577, t, y);

    float2* dst = g_grid2 + ((size_t)b * Kk + row) * Nn;
#pragma unroll
    for (int i = 0; i < 8; i++) {
        int n = i * 64 + t;
        int j = (n < 128) ? (n + 128) : (n - 384);
        if (n < 128 || n >= 384) dst[j] = y[i];
    }
}

// ---------------- FFT pass B: one column per 64-thread block ----------------
__global__ void __launch_bounds__(64) fftB_k() {
    __shared__ float2 s[577];
    __shared__ float swn[2], swx[2];
    int bj = blockIdx.x;            // b*256 + j
    int b = bj >> 8, j = bj & 255;
    const float2* src = g_grid2 + (size_t)b * (Kk * Nn) + j;
    int t = threadIdx.x;
#pragma unroll
    for (int i = 0; i < 8; i++)
        s[PIDX(t + 64 * i)] = src[(size_t)(t + 64 * i) * Nn];
    __syncthreads();

    float2 y[8];
    fft512(s, t, y);

    float ac = apodinv(j);
    float* dst = g_img + ((size_t)b * Nn + j) * Nn;   // [b][c][r]
    float mn = 3.4e38f, mx = -3.4e38f;
#pragma unroll
    for (int i = 0; i < 8; i++) {
        int n = i * 64 + t;
        if (n < 128 || n >= 384) {
            int jr = (n < 128) ? (n + 128) : (n - 384);
            float val = y[i].x * apodinv(jr) * ac;
            dst[jr] = val;
            mn = fminf(mn, val);
            mx = fmaxf(mx, val);
        }
    }
#pragma unroll
    for (int off = 16; off; off >>= 1) {
        mn = fminf(mn, __shfl_xor_sync(0xffffffffu, mn, off));
        mx = fmaxf(mx, __shfl_xor_sync(0xffffffffu, mx, off));
    }
    int w = t >> 5;
    if ((t & 31) == 0) { swn[w] = mn; swx[w] = mx; }
    __syncthreads();
    if (t == 0) {
        mn = fminf(mn, swn[1]); mx = fmaxf(mx, swx[1]);
        atomicMin(&g_mm_i[2 * b], fenc(mn));
        atomicMax(&g_mm_i[2 * b + 1], fenc(mx));
    }
}

// ---------------- normalize + transpose [b][c][r] -> out [b][r][c] ----------
__global__ void __launch_bounds__(256) norm_k(float* __restrict__ out) {
    __shared__ float tile[32][33];
    int b = blockIdx.z;
    int c0 = blockIdx.x * 32, r0 = blockIdx.y * 32;
    int tx = threadIdx.x & 31, ty = threadIdx.x >> 5;

    int emn = g_mm_i[2 * b], emx = g_mm_i[2 * b + 1];
    float mn = __int_as_float(emn < 0 ? (emn ^ 0x7fffffff) : emn);
    float mx = __int_as_float(emx < 0 ? (emx ^ 0x7fffffff) : emx);
    float inv = 1.0f / (mx - mn);

    const float* src = g_img + ((size_t)b << 16);
    float* dst = out + ((size_t)b << 16);
#pragma unroll
    for (int yy = ty; yy < 32; yy += 8)
        tile[yy][tx] = src[(c0 + yy) * Nn + r0 + tx];
    __syncthreads();
#pragma unroll
    for (int yy = ty; yy < 32; yy += 8)
        dst[(r0 + yy) * Nn + c0 + tx] = (tile[tx][yy] - mn) * inv;
}

extern "C" void kernel_launch(void* const* d_in, const int* in_sizes, int n_in,
                              void* d_out, int out_size) {
    const float* yr = (const float*)d_in[0];
    const float* yi = (const float*)d_in[1];
    const float* wt = (const float*)d_in[2];
    const float* uv = (const float*)d_in[3];
    float* out = (float*)d_out;

    prep_k<<<(Mpts + 255) / 256, 256>>>(yr, yi, wt, uv);
    scan_k<<<1, 1024>>>();
    fill_k<<<(Mpts + 255) / 256, 256>>>(uv);
    gather_k<<<NT, 256>>>();
    fftA_k<<<Kk, 512>>>();
    fftB_k<<<Bb * Nn, 64>>>();
    norm_k<<<dim3(8, 8, 8), 256>>>(out);
}

// round 8
// speedup vs baseline: 4.5811x; 4.5811x over previous
#include <cuda_runtime.h>
#include <cuda_fp16.h>
#include <math.h>

#define Mpts 100000
#define Bb 8
#define Kk 512
#define Nn 256

#define BETA_F 13.85510032f       // pi*sqrt((J/ALPHA*(ALPHA-0.5))^2 - 0.8)
#define KSC 81.48733086f          // K/(2*pi)
#define PIJK 0.03681553891f       // pi*J/K

// fp16 grid: [cell][b], 8 complex-half per cell = 32B. 8 MB total.
__device__ __align__(16) __half2 g_gridh[Kk * Kk * Bb];
// row-FFT output, pruned: [b][row(0..511)][j(0..255)]. 8 MB.
__device__ float2 g_grid2[Bb * Kk * Nn];
// real image after col-FFT + apod, TRANSPOSED: [b][c][r]. 2 MB.
__device__ float g_img[Bb * Nn * Nn];
__device__ int g_mm_i[2 * Bb];
// twiddle table: e^{+i 2 pi k/512}
__device__ float2 g_tw[512];

// ---------------- helpers ----------------
__device__ __forceinline__ float2 cmul(float2 a, float2 b) {
    return make_float2(a.x * b.x - a.y * b.y, a.x * b.y + a.y * b.x);
}
__device__ __forceinline__ float2 cadd(float2 a, float2 b) { return make_float2(a.x + b.x, a.y + b.y); }
__device__ __forceinline__ float2 csub(float2 a, float2 b) { return make_float2(a.x - b.x, a.y - b.y); }

__device__ __forceinline__ int fenc(float v) {
    int b = __float_as_int(v);
    return b >= 0 ? b : (b ^ 0x7fffffff);
}

// Bessel I0 (A&S 9.8.1/9.8.2)
__device__ __forceinline__ float i0f(float x) {
    float ax = fabsf(x);
    if (ax < 3.75f) {
        float t = x / 3.75f;
        t *= t;
        return 1.0f + t * (3.5156229f + t * (3.0899424f + t * (1.2067492f +
               t * (0.2659732f + t * (0.0360768f + t * 0.0045813f)))));
    } else {
        float t = 3.75f / ax;
        float p = 0.39894228f + t * (0.01328592f + t * (0.00225319f +
                  t * (-0.00157565f + t * (0.00916281f + t * (-0.02057706f +
                  t * (0.02635537f + t * (-0.01647633f + t * 0.00392377f)))))));
        return (expf(ax) / sqrtf(ax)) * p;
    }
}

__device__ __forceinline__ float apodinv(int n) {
    float x = (float)(n - 128) * PIJK;
    float a = BETA_F * BETA_F - x * x;
    float sq = sqrtf(a);
    return sq / sinhf(sq);
}

// ---------------- twiddle table + minmax init ----------------
__global__ void __launch_bounds__(512) tw_k() {
    int i = threadIdx.x;
    float s, c;
    sincosf(0.01227184630308513f * (float)i, &s, &c);   // 2*pi/512
    g_tw[i] = make_float2(c, s);
    if (i < 2 * Bb)
        g_mm_i[i] = (i & 1) ? (int)0x80000000 : 0x7fffffff;
}

// ---------------- zero grid ----------------
__global__ void __launch_bounds__(256) zero_k() {
    int i = blockIdx.x * 256 + threadIdx.x;  // 524,288 float4 = 8 MB
    reinterpret_cast<float4*>(g_gridh)[i] = make_float4(0.f, 0.f, 0.f, 0.f);
}

// ---------------- gridding scatter: 2 threads per point, fp16 payload -------
// RANGE NOTE: winv is folded into the per-axis WEIGHTS (fp32) so that
// ww = wu*wv in (0,1], and yh = y*wt stays O(1) — both safely in fp16 range.
// (Folding winv^2 into yh underflows fp16: ~1e-10.)
__global__ void __launch_bounds__(256) scatter_k(
    const float* __restrict__ yr, const float* __restrict__ yi,
    const float* __restrict__ wt, const float* __restrict__ uv) {
    int gid = blockIdx.x * 256 + threadIdx.x;
    int m = gid >> 1, q = gid & 1;   // q selects batches {4q..4q+3} (16B half-cell)
    if (m >= Mpts) return;

    float u = uv[2 * m], v = uv[2 * m + 1];
    float kfu = u * KSC, kfv = v * KSC;
    float fbu = floorf(kfu), fbv = floorf(kfv);
    int bu = (int)fbu, bv = (int)fbv;
    float fru = kfu - fbu, frv = kfv - fbv;

    float winv = 1.0f / i0f(BETA_F);

    float wu[6], wv[6];
    int iu[6], iv[6];
#pragma unroll
    for (int o = 0; o < 6; o++) {
        float du = (float)(o - 2) - fru;
        float dv = (float)(o - 2) - frv;
        float uu = du * (1.0f / 3.0f);
        float vv = dv * (1.0f / 3.0f);
        wu[o] = i0f(BETA_F * sqrtf(fmaxf(1.0f - uu * uu, 0.0f))) * winv;
        wv[o] = i0f(BETA_F * sqrtf(fmaxf(1.0f - vv * vv, 0.0f))) * winv;
        iu[o] = (bu + (o - 2) + Kk) & (Kk - 1);
        iv[o] = (bv + (o - 2) + Kk) & (Kk - 1);
    }

    float wm = wt[m];
    int b0 = 4 * q;
    __half2 yh[4];
#pragma unroll
    for (int k = 0; k < 4; k++)
        yh[k] = __floats2half2_rn(yr[(b0 + k) * Mpts + m] * wm,
                                  yi[(b0 + k) * Mpts + m] * wm);

#pragma unroll
    for (int j1 = 0; j1 < 6; j1++) {
        int rb = iu[j1] << 9;
        float w1 = wu[j1];
#pragma unroll
        for (int j2 = 0; j2 < 6; j2++) {
            __half2 wwh = __float2half2_rn(w1 * wv[j2]);
            __half2 p0 = __hmul2(yh[0], wwh);
            __half2 p1 = __hmul2(yh[1], wwh);
            __half2 p2 = __hmul2(yh[2], wwh);
            __half2 p3 = __hmul2(yh[3], wwh);
            unsigned h0 = *reinterpret_cast<unsigned*>(&p0);
            unsigned h1 = *reinterpret_cast<unsigned*>(&p1);
            unsigned h2 = *reinterpret_cast<unsigned*>(&p2);
            unsigned h3 = *reinterpret_cast<unsigned*>(&p3);
            __half2* p = g_gridh + (((unsigned)(rb + iv[j2])) << 3) + (q << 2);
            asm volatile("red.global.add.noftz.v4.f16x2 [%0], {%1,%2,%3,%4};"
                         :: "l"(p), "r"(h0), "r"(h1), "r"(h2), "r"(h3) : "memory");
        }
    }
}

// ---------------- 512-pt inverse FFT, radix-8 Stockham, 64 threads per FFT ----
#define PIDX(i) ((i) + ((i) >> 3))

__device__ __forceinline__ void fft8p(const float2* x, float2* y) {
    const float C = 0.70710678118654752f;
    float2 a0 = cadd(x[0], x[4]), a4 = csub(x[0], x[4]);
    float2 a1 = cadd(x[1], x[5]), t5 = csub(x[1], x[5]);
    float2 a2 = cadd(x[2], x[6]), t6 = csub(x[2], x[6]);
    float2 a3 = cadd(x[3], x[7]), t7 = csub(x[3], x[7]);
    float2 a5 = make_float2(C * (t5.x - t5.y), C * (t5.x + t5.y));
    float2 a6 = make_float2(-t6.y, t6.x);
    float2 a7 = make_float2(-C * (t7.x + t7.y), C * (t7.x - t7.y));

    float2 b0 = cadd(a0, a2), b2 = csub(a0, a2);
    float2 b1 = cadd(a1, a3), t3 = csub(a1, a3);
    float2 b3 = make_float2(-t3.y, t3.x);
    float2 b4 = cadd(a4, a6), b6 = csub(a4, a6);
    float2 b5 = cadd(a5, a7), u7 = csub(a5, a7);
    float2 b7 = make_float2(-u7.y, u7.x);

    y[0] = cadd(b0, b1); y[4] = csub(b0, b1);
    y[2] = cadd(b2, b3); y[6] = csub(b2, b3);
    y[1] = cadd(b4, b5); y[5] = csub(b4, b5);
    y[3] = cadd(b6, b7); y[7] = csub(b6, b7);
}

// 3 Stockham stages with table twiddles; final bins in y (n = i*64+t).
__device__ __forceinline__ void fft512(float2* S, const float2* tw, int t, float2* y) {
    float2 x[8];
#pragma unroll
    for (int i = 0; i < 8; i++) x[i] = S[PIDX(t + 64 * i)];
    fft8p(x, y);
    __syncthreads();
#pragma unroll
    for (int i = 0; i < 8; i++) S[PIDX(8 * t + i)] = y[i];
    __syncthreads();
#pragma unroll
    for (int i = 0; i < 8; i++) x[i] = S[PIDX(t + 64 * i)];
    {
        int k = t & 7;
#pragma unroll
        for (int j = 1; j < 8; j++) x[j] = cmul(x[j], tw[(8 * k * j) & 511]);
    }
    fft8p(x, y);
    __syncthreads();
    {
        int k = t & 7, g = t >> 3;
#pragma unroll
        for (int i = 0; i < 8; i++) S[PIDX(g * 64 + i * 8 + k)] = y[i];
    }
    __syncthreads();
#pragma unroll
    for (int i = 0; i < 8; i++) x[i] = S[PIDX(t + 64 * i)];
#pragma unroll
    for (int j = 1; j < 8; j++) x[j] = cmul(x[j], tw[(t * j) & 511]);
    fft8p(x, y);
}

// ---------------- FFT pass A: along axis 2 (columns). 8 batches / block -----
__global__ void __launch_bounds__(512) fftA_k() {
    __shared__ float2 s[8 * 577];
    __shared__ float2 s_tw[512];
    int row = blockIdx.x;
    s_tw[threadIdx.x] = g_tw[threadIdx.x];
    const uint4* src = reinterpret_cast<const uint4*>(g_gridh + (size_t)row * (Kk * Bb));
    for (int idx = threadIdx.x; idx < Kk * 2; idx += 512) {
        int col = idx >> 1, q = idx & 1;      // uint4 = 4 complex-halves (batches 4q..4q+3)
        uint4 val = src[idx];
        __half2 h0 = *reinterpret_cast<__half2*>(&val.x);
        __half2 h1 = *reinterpret_cast<__half2*>(&val.y);
        __half2 h2 = *reinterpret_cast<__half2*>(&val.z);
        __half2 h3 = *reinterpret_cast<__half2*>(&val.w);
        int bq = 4 * q;
        s[(bq + 0) * 577 + PIDX(col)] = __half22float2(h0);
        s[(bq + 1) * 577 + PIDX(col)] = __half22float2(h1);
        s[(bq + 2) * 577 + PIDX(col)] = __half22float2(h2);
        s[(bq + 3) * 577 + PIDX(col)] = __half22float2(h3);
    }
    __syncthreads();

    int b = threadIdx.x >> 6, t = threadIdx.x & 63;
    float2 y[8];
    fft512(s + b * 577, s_tw, t, y);

    float2* dst = g_grid2 + ((size_t)b * Kk + row) * Nn;
#pragma unroll
    for (int i = 0; i < 8; i++) {
        int n = i * 64 + t;
        int j = (n < 128) ? (n + 128) : (n - 384);
        if (n < 128 || n >= 384) dst[j] = y[i];
    }
}

// ---------------- FFT pass B: one column per 64-thread block ----------------
__global__ void __launch_bounds__(64) fftB_k() {
    __shared__ float2 s[577];
    __shared__ float2 s_tw[512];
    __shared__ float swn[2], swx[2];
    int bj = blockIdx.x;            // b*256 + j
    int b = bj >> 8, j = bj & 255;
    const float2* src = g_grid2 + (size_t)b * (Kk * Nn) + j;
    int t = threadIdx.x;
#pragma unroll
    for (int i = 0; i < 8; i++) {
        s_tw[t + 64 * i] = g_tw[t + 64 * i];
        s[PIDX(t + 64 * i)] = src[(size_t)(t + 64 * i) * Nn];
    }
    __syncthreads();

    float2 y[8];
    fft512(s, s_tw, t, y);

    float ac = apodinv(j);
    float* dst = g_img + ((size_t)b * Nn + j) * Nn;   // [b][c][r]
    float mn = 3.4e38f, mx = -3.4e38f;
#pragma unroll
    for (int i = 0; i < 8; i++) {
        int n = i * 64 + t;
        if (n < 128 || n >= 384) {
            int jr = (n < 128) ? (n + 128) : (n - 384);
            float val = y[i].x * apodinv(jr) * ac;
            dst[jr] = val;
            mn = fminf(mn, val);
            mx = fmaxf(mx, val);
        }
    }
#pragma unroll
    for (int off = 16; off; off >>= 1) {
        mn = fminf(mn, __shfl_xor_sync(0xffffffffu, mn, off));
        mx = fmaxf(mx, __shfl_xor_sync(0xffffffffu, mx, off));
    }
    int w = t >> 5;
    if ((t & 31) == 0) { swn[w] = mn; swx[w] = mx; }
    __syncthreads();
    if (t == 0) {
        mn = fminf(mn, swn[1]); mx = fmaxf(mx, swx[1]);
        atomicMin(&g_mm_i[2 * b], fenc(mn));
        atomicMax(&g_mm_i[2 * b + 1], fenc(mx));
    }
}

// ---------------- normalize + transpose [b][c][r] -> out [b][r][c] ----------
__global__ void __launch_bounds__(256) norm_k(float* __restrict__ out) {
    __shared__ float tile[32][33];
    int b = blockIdx.z;
    int c0 = blockIdx.x * 32, r0 = blockIdx.y * 32;
    int tx = threadIdx.x & 31, ty = threadIdx.x >> 5;

    int emn = g_mm_i[2 * b], emx = g_mm_i[2 * b + 1];
    float mn = __int_as_float(emn < 0 ? (emn ^ 0x7fffffff) : emn);
    float mx = __int_as_float(emx < 0 ? (emx ^ 0x7fffffff) : emx);
    float inv = 1.0f / (mx - mn);

    const float* src = g_img + ((size_t)b << 16);
    float* dst = out + ((size_t)b << 16);
#pragma unroll
    for (int yy = ty; yy < 32; yy += 8)
        tile[yy][tx] = src[(c0 + yy) * Nn + r0 + tx];
    __syncthreads();
#pragma unroll
    for (int yy = ty; yy < 32; yy += 8)
        dst[(r0 + yy) * Nn + c0 + tx] = (tile[tx][yy] - mn) * inv;
}

extern "C" void kernel_launch(void* const* d_in, const int* in_sizes, int n_in,
                              void* d_out, int out_size) {
    const float* yr = (const float*)d_in[0];
    const float* yi = (const float*)d_in[1];
    const float* wt = (const float*)d_in[2];
    const float* uv = (const float*)d_in[3];
    float* out = (float*)d_out;

    tw_k<<<1, 512>>>();
    zero_k<<<2048, 256>>>();
    scatter_k<<<(2 * Mpts + 255) / 256, 256>>>(yr, yi, wt, uv);
    fftA_k<<<Kk, 512>>>();
    fftB_k<<<Bb * Nn, 64>>>();
    norm_k<<<dim3(8, 8, 8), 256>>>(out);
}